// round 3
// baseline (speedup 1.0000x reference)
#include <cuda_runtime.h>
#include <cuda_bf16.h>
#include <cstdint>
#include <cstddef>

#define MAXN 50000
#define HDIM 128

// -------------------- scratch --------------------
__device__ float g_h[(size_t)MAXN * HDIM];
__device__ float g_B[(size_t)MAXN * HDIM];
__device__ float g_C[(size_t)MAXN * HDIM];
__device__ int   g_cnt[MAXN];
__device__ float g_coef[MAXN];

// -------------------- helpers --------------------
__device__ __forceinline__ uint32_t smem_u32(const void* p) {
    uint32_t a;
    asm("{ .reg .u64 t; cvta.to.shared.u64 t, %1; cvt.u32.u64 %0, t; }" : "=r"(a) : "l"(p));
    return a;
}

__device__ __forceinline__ void red_add_v4(float* p, float a, float b, float c, float d) {
    asm volatile("red.global.add.v4.f32 [%0], {%1,%2,%3,%4};"
                 :: "l"(p), "f"(a), "f"(b), "f"(c), "f"(d) : "memory");
}

__device__ __forceinline__ void ldsm4(uint32_t* r, uint32_t addr) {
    asm volatile("ldmatrix.sync.aligned.m8n8.x4.shared.b16 {%0,%1,%2,%3}, [%4];"
                 : "=r"(r[0]), "=r"(r[1]), "=r"(r[2]), "=r"(r[3]) : "r"(addr));
}

__device__ __forceinline__ void mma_bf16(float* c, const uint32_t* a, uint32_t b0, uint32_t b1) {
    asm volatile("mma.sync.aligned.m16n8k16.row.col.f32.bf16.bf16.f32 "
                 "{%0,%1,%2,%3}, {%4,%5,%6,%7}, {%8,%9}, {%0,%1,%2,%3};"
                 : "+f"(c[0]), "+f"(c[1]), "+f"(c[2]), "+f"(c[3])
                 : "r"(a[0]), "r"(a[1]), "r"(a[2]), "r"(a[3]), "r"(b0), "r"(b1));
}

// padded row-major bf16 tile: row stride 136 bf16 = 272 bytes (conflict-free ldmatrix)
#define RSTRIDE 272
__device__ __forceinline__ uint32_t toff(int r, int k) {
    return (uint32_t)r * RSTRIDE + (uint32_t)k * 2;
}

// split fp32 float4 -> bf16 hi + bf16 lo, store 4 consecutive k
__device__ __forceinline__ void cvt_store(char* hi, char* lo, uint32_t off, float4 v) {
    __nv_bfloat162 h01 = __floats2bfloat162_rn(v.x, v.y);
    float2 f01 = __bfloat1622float2(h01);
    __nv_bfloat162 l01 = __floats2bfloat162_rn(v.x - f01.x, v.y - f01.y);
    __nv_bfloat162 h23 = __floats2bfloat162_rn(v.z, v.w);
    float2 f23 = __bfloat1622float2(h23);
    __nv_bfloat162 l23 = __floats2bfloat162_rn(v.z - f23.x, v.w - f23.y);
    *(uint32_t*)(hi + off)     = *(uint32_t*)&h01;
    *(uint32_t*)(hi + off + 4) = *(uint32_t*)&h23;
    *(uint32_t*)(lo + off)     = *(uint32_t*)&l01;
    *(uint32_t*)(lo + off + 4) = *(uint32_t*)&l23;
}

// -------------------- HMMA GEMM: C[M,BN] = A[M,128] @ W[BN,128]^T + bias --------------------
// Block: 128 rows, 256 threads (8 warps: 4 along M x 2 along N). bf16 hi/lo, 3 passes.
template<int BN, bool RELU>
__global__ __launch_bounds__(256, 1) void gemm_mma(
    const float* __restrict__ A, const float* __restrict__ W,
    const float* __restrict__ bias, float* __restrict__ C, int M)
{
    constexpr int WN  = BN / 2;          // warp tile N (64 or 32)
    constexpr int NT8 = WN / 8;          // n8 tiles per warp (8 or 4)
    constexpr int AT  = 128 * RSTRIDE;   // 34816 B
    constexpr int WT  = BN * RSTRIDE;
    constexpr int OFF_WHI = 0;
    constexpr int OFF_WLO = WT;
    constexpr int OFF_AHI = 2 * WT;
    constexpr int OFF_ALO = 2 * WT + AT;

    extern __shared__ __align__(16) char smem[];
    const uint32_t sb = smem_u32(smem);
    const int tid = threadIdx.x, wid = tid >> 5, lane = tid & 31;
    const int row0 = blockIdx.x * 128;
    const int warp_m0 = (wid & 3) * 32;
    const int warp_n0 = (wid >> 2) * WN;

    // ---- stage W (hi/lo) ----
    for (int i = tid; i < BN * 32; i += 256) {
        int r = i >> 5, k = (i & 31) * 4;
        float4 v = *(const float4*)(W + (size_t)r * 128 + k);
        cvt_store(smem + OFF_WHI, smem + OFF_WLO, toff(r, k), v);
    }
    // ---- stage A (hi/lo) ----
    for (int i = tid; i < 128 * 32; i += 256) {
        int r = i >> 5, k = (i & 31) * 4;
        float4 v = make_float4(0.f, 0.f, 0.f, 0.f);
        if (row0 + r < M) v = *(const float4*)(A + (size_t)(row0 + r) * 128 + k);
        cvt_store(smem + OFF_AHI, smem + OFF_ALO, toff(r, k), v);
    }
    __syncthreads();

    // ldmatrix per-thread offsets
    const int arow = (lane & 7) + ((lane >> 3) & 1) * 8;
    const int ak   = (lane >> 4) * 8;
    const uint32_t aoff = (uint32_t)(warp_m0 + arow) * RSTRIDE + (uint32_t)ak * 2;
    const int brow = (lane & 7) + (lane >> 4) * 8;
    const int bk   = ((lane >> 3) & 1) * 8;
    const uint32_t boff = (uint32_t)(warp_n0 + brow) * RSTRIDE + (uint32_t)bk * 2;

    float acc[2][NT8][4];
    #pragma unroll
    for (int mt = 0; mt < 2; mt++)
        #pragma unroll
        for (int nt = 0; nt < NT8; nt++)
            #pragma unroll
            for (int q = 0; q < 4; q++) acc[mt][nt][q] = 0.f;

    const uint32_t aBases[3] = { sb + OFF_AHI + aoff, sb + OFF_AHI + aoff, sb + OFF_ALO + aoff };
    const uint32_t bBases[3] = { sb + OFF_WHI + boff, sb + OFF_WLO + boff, sb + OFF_WHI + boff };

    #pragma unroll
    for (int p = 0; p < 3; p++) {
        uint32_t aB = aBases[p], bB = bBases[p];
        #pragma unroll
        for (int ks = 0; ks < 8; ks++) {
            uint32_t af[8];
            ldsm4(af,     aB + ks * 32);
            ldsm4(af + 4, aB + 16 * RSTRIDE + ks * 32);
            uint32_t bf[NT8 * 2];
            #pragma unroll
            for (int nt2 = 0; nt2 < NT8 / 2; nt2++)
                ldsm4(bf + nt2 * 4, bB + nt2 * 16 * RSTRIDE + ks * 32);
            #pragma unroll
            for (int mt = 0; mt < 2; mt++)
                #pragma unroll
                for (int nt = 0; nt < NT8; nt++)
                    mma_bf16(acc[mt][nt], af + mt * 4, bf[nt * 2], bf[nt * 2 + 1]);
        }
    }

    // ---- epilogue: direct gmem stores ----
    const int colq = (lane & 3) * 2;
    #pragma unroll
    for (int mt = 0; mt < 2; mt++) {
        int r0 = row0 + warp_m0 + mt * 16 + (lane >> 2);
        #pragma unroll
        for (int nt = 0; nt < NT8; nt++) {
            int col = warp_n0 + nt * 8 + colq;
            float2 b2 = *(const float2*)(bias + col);
            float2 o0, o1;
            o0.x = acc[mt][nt][0] + b2.x; o0.y = acc[mt][nt][1] + b2.y;
            o1.x = acc[mt][nt][2] + b2.x; o1.y = acc[mt][nt][3] + b2.y;
            if (RELU) {
                o0.x = fmaxf(o0.x, 0.f); o0.y = fmaxf(o0.y, 0.f);
                o1.x = fmaxf(o1.x, 0.f); o1.y = fmaxf(o1.y, 0.f);
            }
            if (r0 < M)     *(float2*)(C + (size_t)r0 * BN + col)       = o0;
            if (r0 + 8 < M) *(float2*)(C + (size_t)(r0 + 8) * BN + col) = o1;
        }
    }
}

// -------------------- attention (exact: uniform softmax = 1/(deg_out+1)) --------------------
__global__ void cnt_init_kernel(int n) {
    int i = blockIdx.x * blockDim.x + threadIdx.x;
    if (i < n) g_cnt[i] = 1;   // self loop
}
__global__ void cnt_edge_kernel(const int* __restrict__ row, int E) {
    int e = blockIdx.x * blockDim.x + threadIdx.x;
    if (e < E) atomicAdd(&g_cnt[row[e]], 1);
}
__global__ void self_msg_kernel(int n) {
    int idx = blockIdx.x * blockDim.x + threadIdx.x;
    if (idx >= n * 32) return;
    int i = idx >> 5;
    float coef = 1.0f / (float)g_cnt[i];
    if ((idx & 31) == 0) g_coef[i] = coef;
    float4 v = *(const float4*)(g_h + (size_t)i * 128 + (idx & 31) * 4);
    v.x *= coef; v.y *= coef; v.z *= coef; v.w *= coef;
    *(float4*)(g_B + (size_t)i * 128 + (idx & 31) * 4) = v;
}
__global__ void edge_msg_kernel(const int* __restrict__ row, const int* __restrict__ col, int E) {
    int e = (blockIdx.x * blockDim.x + threadIdx.x) >> 5;
    int lane = threadIdx.x & 31;
    if (e >= E) return;
    int r = row[e], c = col[e];
    float coef = g_coef[r];
    float4 v = *(const float4*)(g_h + (size_t)r * 128 + lane * 4);
    red_add_v4(g_B + (size_t)c * 128 + lane * 4,
               coef * v.x, coef * v.y, coef * v.z, coef * v.w);
}
__global__ void edge_agg_kernel(const int* __restrict__ row, const int* __restrict__ col,
                                const float* __restrict__ src, float* __restrict__ dst, int E) {
    int e = (blockIdx.x * blockDim.x + threadIdx.x) >> 5;
    int lane = threadIdx.x & 31;
    if (e >= E) return;
    int r = row[e], c = col[e];
    float4 v = *(const float4*)(src + (size_t)r * 128 + lane * 4);
    red_add_v4(dst + (size_t)c * 128 + lane * 4, v.x, v.y, v.z, v.w);
}

__global__ void relu_copy_kernel(float* __restrict__ x, float* __restrict__ dst, size_t n4) {
    size_t i = (size_t)blockIdx.x * blockDim.x + threadIdx.x;
    if (i >= n4) return;
    float4 v = *(float4*)(x + i * 4);
    v.x = fmaxf(v.x, 0.f); v.y = fmaxf(v.y, 0.f);
    v.z = fmaxf(v.z, 0.f); v.w = fmaxf(v.w, 0.f);
    *(float4*)(x + i * 4) = v;
    *(float4*)(dst + i * 4) = v;
}
__global__ void copy_kernel(float* __restrict__ dst, const float* __restrict__ src, size_t n4) {
    size_t i = (size_t)blockIdx.x * blockDim.x + threadIdx.x;
    if (i >= n4) return;
    *(float4*)(dst + i * 4) = *(const float4*)(src + i * 4);
}

__global__ void lsm_kernel(float* __restrict__ out, int n) {
    int r = (blockIdx.x * blockDim.x + threadIdx.x) >> 5;
    int lane = threadIdx.x & 31;
    if (r >= n) return;
    float x0 = out[(size_t)r * 64 + lane];
    float x1 = out[(size_t)r * 64 + 32 + lane];
    float m = fmaxf(x0, x1);
    #pragma unroll
    for (int o = 16; o; o >>= 1) m = fmaxf(m, __shfl_xor_sync(0xffffffffu, m, o));
    float s = expf(x0 - m) + expf(x1 - m);
    #pragma unroll
    for (int o = 16; o; o >>= 1) s += __shfl_xor_sync(0xffffffffu, s, o);
    float ls = logf(s) + m;
    out[(size_t)r * 64 + lane]      = x0 - ls;
    out[(size_t)r * 64 + 32 + lane] = x1 - ls;
}

// -------------------- launch --------------------
extern "C" void kernel_launch(void* const* d_in, const int* in_sizes, int n_in,
                              void* d_out, int out_size)
{
    const float* x     = (const float*)d_in[0];
    const int*   ei    = (const int*)  d_in[1];
    const float* fl_W  = (const float*)d_in[2];
    const float* fl_b  = (const float*)d_in[3];
    // d_in[4] = fl_att : softmax of identical per-segment logits is uniform -> att unused
    const float* g1_W1 = (const float*)d_in[5];
    const float* g1_b1 = (const float*)d_in[6];
    const float* g1_W2 = (const float*)d_in[7];
    const float* g1_b2 = (const float*)d_in[8];
    const float* g2_W1 = (const float*)d_in[9];
    const float* g2_b1 = (const float*)d_in[10];
    const float* g2_W2 = (const float*)d_in[11];
    const float* g2_b2 = (const float*)d_in[12];
    const float* out_W = (const float*)d_in[13];
    const float* out_b = (const float*)d_in[14];
    float* out = (float*)d_out;

    const int N = in_sizes[0] / HDIM;
    const int E = in_sizes[1] / 2;
    const int* row = ei;
    const int* col = ei + E;

    float *pH = nullptr, *pB = nullptr, *pC = nullptr;
    cudaGetSymbolAddress((void**)&pH, g_h);
    cudaGetSymbolAddress((void**)&pB, g_B);
    cudaGetSymbolAddress((void**)&pC, g_C);

    const int AT = 128 * RSTRIDE;
    const int smem128 = 2 * (128 * RSTRIDE) + 2 * AT;  // 139264
    const int smem64  = 2 * (64 * RSTRIDE) + 2 * AT;   // 104448
    cudaFuncSetAttribute(gemm_mma<128, false>, cudaFuncAttributeMaxDynamicSharedMemorySize, smem128);
    cudaFuncSetAttribute(gemm_mma<128, true>,  cudaFuncAttributeMaxDynamicSharedMemorySize, smem128);
    cudaFuncSetAttribute(gemm_mma<64, false>,  cudaFuncAttributeMaxDynamicSharedMemorySize, smem64);

    const int T = 256;
    const int gemmGrid  = (N + 127) / 128;
    const int edgeWarpG = (E * 32 + T - 1) / T;
    const int edgeThG   = (E + T - 1) / T;
    const int nodeThG   = (N + T - 1) / T;
    const int nodeVecG  = (N * 32 + T - 1) / T;
    const size_t n4     = (size_t)N * 32;
    const int vecG      = (int)((n4 + T - 1) / T);

    // 1. h = x @ fl_W^T + fl_b
    gemm_mma<128, false><<<gemmGrid, T, smem128>>>(x, fl_W, fl_b, pH, N);
    // 2-3. out-degree (incl self loop) -> uniform attention coef
    cnt_init_kernel<<<nodeThG, T>>>(N);
    cnt_edge_kernel<<<edgeThG, T>>>(row, E);
    // 4-6. weighted aggregation -> B, relu, copy to C
    self_msg_kernel<<<nodeVecG, T>>>(N);
    edge_msg_kernel<<<edgeWarpG, T>>>(row, col, E);
    relu_copy_kernel<<<vecG, T>>>(pB, pC, n4);
    // 7-9. GIN layer 1
    edge_agg_kernel<<<edgeWarpG, T>>>(row, col, pB, pC, E);
    gemm_mma<128, true><<<gemmGrid, T, smem128>>>(pC, g1_W1, g1_b1, pH, N);
    gemm_mma<128, true><<<gemmGrid, T, smem128>>>(pH, g1_W2, g1_b2, pC, N);
    // 10-13. GIN layer 2
    copy_kernel<<<vecG, T>>>(pB, pC, n4);
    edge_agg_kernel<<<edgeWarpG, T>>>(row, col, pC, pB, E);
    gemm_mma<128, true><<<gemmGrid, T, smem128>>>(pB, g2_W1, g2_b1, pH, N);
    gemm_mma<128, true><<<gemmGrid, T, smem128>>>(pH, g2_W2, g2_b2, pB, N);
    // 14-15. output head + log_softmax
    gemm_mma<64, false><<<gemmGrid, T, smem64>>>(pB, out_W, out_b, out, N);
    lsm_kernel<<<nodeVecG, T>>>(out, N);
}

// round 4
// speedup vs baseline: 1.3945x; 1.3945x over previous
#include <cuda_runtime.h>
#include <cuda_bf16.h>
#include <cstdint>
#include <cstddef>

#define MAXN 50000
#define MAXE 600000
#define HDIM 128

// -------------------- scratch --------------------
__device__ float g_h[(size_t)MAXN * HDIM];
__device__ float g_B[(size_t)MAXN * HDIM];
__device__ float g_C[(size_t)MAXN * HDIM];
__device__ int   g_indeg[MAXN];
__device__ int   g_outdeg[MAXN];
__device__ float g_coef[MAXN];
__device__ int   g_start[MAXN];    // CSR row start (by destination)
__device__ int   g_ptr[MAXN];      // scatter cursor
__device__ int   g_eid[MAXE];      // source node of each CSR slot
__device__ int   g_blocksum[64];

// -------------------- helpers --------------------
__device__ __forceinline__ uint32_t smem_u32(const void* p) {
    uint32_t a;
    asm("{ .reg .u64 t; cvta.to.shared.u64 t, %1; cvt.u32.u64 %0, t; }" : "=r"(a) : "l"(p));
    return a;
}
__device__ __forceinline__ void ldsm4(uint32_t* r, uint32_t addr) {
    asm volatile("ldmatrix.sync.aligned.m8n8.x4.shared.b16 {%0,%1,%2,%3}, [%4];"
                 : "=r"(r[0]), "=r"(r[1]), "=r"(r[2]), "=r"(r[3]) : "r"(addr));
}
__device__ __forceinline__ void mma_bf16(float* c, const uint32_t* a, uint32_t b0, uint32_t b1) {
    asm volatile("mma.sync.aligned.m16n8k16.row.col.f32.bf16.bf16.f32 "
                 "{%0,%1,%2,%3}, {%4,%5,%6,%7}, {%8,%9}, {%0,%1,%2,%3};"
                 : "+f"(c[0]), "+f"(c[1]), "+f"(c[2]), "+f"(c[3])
                 : "r"(a[0]), "r"(a[1]), "r"(a[2]), "r"(a[3]), "r"(b0), "r"(b1));
}

#define RSTRIDE 272
__device__ __forceinline__ uint32_t toff(int r, int k) {
    return (uint32_t)r * RSTRIDE + (uint32_t)k * 2;
}
__device__ __forceinline__ void cvt_store(char* hi, char* lo, uint32_t off, float4 v) {
    __nv_bfloat162 h01 = __floats2bfloat162_rn(v.x, v.y);
    float2 f01 = __bfloat1622float2(h01);
    __nv_bfloat162 l01 = __floats2bfloat162_rn(v.x - f01.x, v.y - f01.y);
    __nv_bfloat162 h23 = __floats2bfloat162_rn(v.z, v.w);
    float2 f23 = __bfloat1622float2(h23);
    __nv_bfloat162 l23 = __floats2bfloat162_rn(v.z - f23.x, v.w - f23.y);
    *(uint32_t*)(hi + off)     = *(uint32_t*)&h01;
    *(uint32_t*)(hi + off + 4) = *(uint32_t*)&h23;
    *(uint32_t*)(lo + off)     = *(uint32_t*)&l01;
    *(uint32_t*)(lo + off + 4) = *(uint32_t*)&l23;
}

// -------------------- HMMA GEMM: C[M,BN] = A[M,128] @ W[BN,128]^T + bias --------------------
template<int BN, bool RELU>
__global__ __launch_bounds__(256, 1) void gemm_mma(
    const float* __restrict__ A, const float* __restrict__ W,
    const float* __restrict__ bias, float* __restrict__ C, int M)
{
    constexpr int WN  = BN / 2;
    constexpr int NT8 = WN / 8;
    constexpr int AT  = 128 * RSTRIDE;
    constexpr int WT  = BN * RSTRIDE;
    constexpr int OFF_WHI = 0;
    constexpr int OFF_WLO = WT;
    constexpr int OFF_AHI = 2 * WT;
    constexpr int OFF_ALO = 2 * WT + AT;

    extern __shared__ __align__(16) char smem[];
    const uint32_t sb = smem_u32(smem);
    const int tid = threadIdx.x, wid = tid >> 5, lane = tid & 31;
    const int row0 = blockIdx.x * 128;
    const int warp_m0 = (wid & 3) * 32;
    const int warp_n0 = (wid >> 2) * WN;

    for (int i = tid; i < BN * 32; i += 256) {
        int r = i >> 5, k = (i & 31) * 4;
        float4 v = *(const float4*)(W + (size_t)r * 128 + k);
        cvt_store(smem + OFF_WHI, smem + OFF_WLO, toff(r, k), v);
    }
    for (int i = tid; i < 128 * 32; i += 256) {
        int r = i >> 5, k = (i & 31) * 4;
        float4 v = make_float4(0.f, 0.f, 0.f, 0.f);
        if (row0 + r < M) v = *(const float4*)(A + (size_t)(row0 + r) * 128 + k);
        cvt_store(smem + OFF_AHI, smem + OFF_ALO, toff(r, k), v);
    }
    __syncthreads();

    const int arow = (lane & 7) + ((lane >> 3) & 1) * 8;
    const int ak   = (lane >> 4) * 8;
    const uint32_t aoff = (uint32_t)(warp_m0 + arow) * RSTRIDE + (uint32_t)ak * 2;
    const int brow = (lane & 7) + (lane >> 4) * 8;
    const int bk   = ((lane >> 3) & 1) * 8;
    const uint32_t boff = (uint32_t)(warp_n0 + brow) * RSTRIDE + (uint32_t)bk * 2;

    float acc[2][NT8][4];
    #pragma unroll
    for (int mt = 0; mt < 2; mt++)
        #pragma unroll
        for (int nt = 0; nt < NT8; nt++)
            #pragma unroll
            for (int q = 0; q < 4; q++) acc[mt][nt][q] = 0.f;

    const uint32_t aBases[3] = { sb + OFF_AHI + aoff, sb + OFF_AHI + aoff, sb + OFF_ALO + aoff };
    const uint32_t bBases[3] = { sb + OFF_WHI + boff, sb + OFF_WLO + boff, sb + OFF_WHI + boff };

    #pragma unroll
    for (int p = 0; p < 3; p++) {
        uint32_t aB = aBases[p], bB = bBases[p];
        #pragma unroll
        for (int ks = 0; ks < 8; ks++) {
            uint32_t af[8];
            ldsm4(af,     aB + ks * 32);
            ldsm4(af + 4, aB + 16 * RSTRIDE + ks * 32);
            uint32_t bf[NT8 * 2];
            #pragma unroll
            for (int nt2 = 0; nt2 < NT8 / 2; nt2++)
                ldsm4(bf + nt2 * 4, bB + nt2 * 16 * RSTRIDE + ks * 32);
            #pragma unroll
            for (int mt = 0; mt < 2; mt++)
                #pragma unroll
                for (int nt = 0; nt < NT8; nt++)
                    mma_bf16(acc[mt][nt], af + mt * 4, bf[nt * 2], bf[nt * 2 + 1]);
        }
    }

    const int colq = (lane & 3) * 2;
    #pragma unroll
    for (int mt = 0; mt < 2; mt++) {
        int r0 = row0 + warp_m0 + mt * 16 + (lane >> 2);
        #pragma unroll
        for (int nt = 0; nt < NT8; nt++) {
            int col = warp_n0 + nt * 8 + colq;
            float2 b2 = *(const float2*)(bias + col);
            float2 o0, o1;
            o0.x = acc[mt][nt][0] + b2.x; o0.y = acc[mt][nt][1] + b2.y;
            o1.x = acc[mt][nt][2] + b2.x; o1.y = acc[mt][nt][3] + b2.y;
            if (RELU) {
                o0.x = fmaxf(o0.x, 0.f); o0.y = fmaxf(o0.y, 0.f);
                o1.x = fmaxf(o1.x, 0.f); o1.y = fmaxf(o1.y, 0.f);
            }
            if (r0 < M)     *(float2*)(C + (size_t)r0 * BN + col)       = o0;
            if (r0 + 8 < M) *(float2*)(C + (size_t)(r0 + 8) * BN + col) = o1;
        }
    }
}

// -------------------- CSR build --------------------
__global__ void zero_deg_kernel(int n) {
    int i = blockIdx.x * blockDim.x + threadIdx.x;
    if (i < n) { g_indeg[i] = 0; g_outdeg[i] = 0; }
}
__global__ void hist_kernel(const int* __restrict__ row, const int* __restrict__ col, int E) {
    int e = blockIdx.x * blockDim.x + threadIdx.x;
    if (e >= E) return;
    atomicAdd(&g_indeg[col[e]], 1);
    atomicAdd(&g_outdeg[row[e]], 1);
}
__global__ void coef_kernel(int n) {
    int i = blockIdx.x * blockDim.x + threadIdx.x;
    if (i < n) g_coef[i] = 1.0f / (float)(g_outdeg[i] + 1);  // +1 self loop
}
// block-wise exclusive scan of g_indeg (1024 elems/block)
__global__ __launch_bounds__(1024) void scan_block_kernel(int* __restrict__ out, int n) {
    __shared__ int wsum[32];
    int i = blockIdx.x * 1024 + threadIdx.x;
    int lane = threadIdx.x & 31, wid = threadIdx.x >> 5;
    int orig = (i < n) ? g_indeg[i] : 0;
    int v = orig;
    #pragma unroll
    for (int o = 1; o < 32; o <<= 1) {
        int t = __shfl_up_sync(0xffffffffu, v, o);
        if (lane >= o) v += t;
    }
    if (lane == 31) wsum[wid] = v;
    __syncthreads();
    if (wid == 0) {
        int s = wsum[lane];
        #pragma unroll
        for (int o = 1; o < 32; o <<= 1) {
            int t = __shfl_up_sync(0xffffffffu, s, o);
            if (lane >= o) s += t;
        }
        wsum[lane] = s;
    }
    __syncthreads();
    int excl = v - orig + (wid > 0 ? wsum[wid - 1] : 0);
    if (i < n) out[i] = excl;
    if (threadIdx.x == 1023) g_blocksum[blockIdx.x] = excl + orig;
}
__global__ void scan_top_kernel(int nb) {
    if (threadIdx.x == 0) {
        int acc = 0;
        for (int b = 0; b < nb; b++) { int t = g_blocksum[b]; g_blocksum[b] = acc; acc += t; }
    }
}
__global__ void finalize_kernel(const int* __restrict__ partial, int n) {
    int i = blockIdx.x * blockDim.x + threadIdx.x;
    if (i >= n) return;
    int s = partial[i] + g_blocksum[i >> 10];
    g_start[i] = s;
    g_ptr[i]   = s;
}
__global__ void scatter_kernel(const int* __restrict__ row, const int* __restrict__ col, int E) {
    int e = blockIdx.x * blockDim.x + threadIdx.x;
    if (e >= E) return;
    int p = atomicAdd(&g_ptr[col[e]], 1);
    g_eid[p] = row[e];
}

// -------------------- gather aggregation (warp per node) --------------------
// ATT:  dst[i] = relu( coef[i]*src[i] + sum_in coef[s]*src[s] )
// GIN:  dst[i] = src[i] + sum_in src[s]
template<bool ATT>
__global__ void agg_kernel(const float* __restrict__ src, float* __restrict__ dst, int n) {
    int node = (blockIdx.x * blockDim.x + threadIdx.x) >> 5;
    int lane = threadIdx.x & 31;
    if (node >= n) return;
    int s = g_start[node], e = s + g_indeg[node];
    float4 acc = *(const float4*)(src + (size_t)node * 128 + lane * 4);
    if (ATT) {
        float c = g_coef[node];
        acc.x *= c; acc.y *= c; acc.z *= c; acc.w *= c;
    }
    for (int j = s; j < e; j++) {
        int r = __ldg(&g_eid[j]);
        float4 v = *(const float4*)(src + (size_t)r * 128 + lane * 4);
        float c = ATT ? g_coef[r] : 1.0f;
        acc.x = fmaf(c, v.x, acc.x); acc.y = fmaf(c, v.y, acc.y);
        acc.z = fmaf(c, v.z, acc.z); acc.w = fmaf(c, v.w, acc.w);
    }
    if (ATT) {
        acc.x = fmaxf(acc.x, 0.f); acc.y = fmaxf(acc.y, 0.f);
        acc.z = fmaxf(acc.z, 0.f); acc.w = fmaxf(acc.w, 0.f);
    }
    *(float4*)(dst + (size_t)node * 128 + lane * 4) = acc;
}

// -------------------- log_softmax --------------------
__global__ void lsm_kernel(float* __restrict__ out, int n) {
    int r = (blockIdx.x * blockDim.x + threadIdx.x) >> 5;
    int lane = threadIdx.x & 31;
    if (r >= n) return;
    float x0 = out[(size_t)r * 64 + lane];
    float x1 = out[(size_t)r * 64 + 32 + lane];
    float m = fmaxf(x0, x1);
    #pragma unroll
    for (int o = 16; o; o >>= 1) m = fmaxf(m, __shfl_xor_sync(0xffffffffu, m, o));
    float s = expf(x0 - m) + expf(x1 - m);
    #pragma unroll
    for (int o = 16; o; o >>= 1) s += __shfl_xor_sync(0xffffffffu, s, o);
    float ls = logf(s) + m;
    out[(size_t)r * 64 + lane]      = x0 - ls;
    out[(size_t)r * 64 + 32 + lane] = x1 - ls;
}

// -------------------- launch --------------------
extern "C" void kernel_launch(void* const* d_in, const int* in_sizes, int n_in,
                              void* d_out, int out_size)
{
    const float* x     = (const float*)d_in[0];
    const int*   ei    = (const int*)  d_in[1];
    const float* fl_W  = (const float*)d_in[2];
    const float* fl_b  = (const float*)d_in[3];
    // d_in[4] = fl_att : softmax of identical per-segment logits is uniform -> unused
    const float* g1_W1 = (const float*)d_in[5];
    const float* g1_b1 = (const float*)d_in[6];
    const float* g1_W2 = (const float*)d_in[7];
    const float* g1_b2 = (const float*)d_in[8];
    const float* g2_W1 = (const float*)d_in[9];
    const float* g2_b1 = (const float*)d_in[10];
    const float* g2_W2 = (const float*)d_in[11];
    const float* g2_b2 = (const float*)d_in[12];
    const float* out_W = (const float*)d_in[13];
    const float* out_b = (const float*)d_in[14];
    float* out = (float*)d_out;

    const int N = in_sizes[0] / HDIM;
    const int E = in_sizes[1] / 2;
    const int* row = ei;
    const int* col = ei + E;

    float *pH = nullptr, *pB = nullptr, *pC = nullptr;
    int* pPtr = nullptr;  // reuse g_ptr buffer as scan partial output
    cudaGetSymbolAddress((void**)&pH, g_h);
    cudaGetSymbolAddress((void**)&pB, g_B);
    cudaGetSymbolAddress((void**)&pC, g_C);
    cudaGetSymbolAddress((void**)&pPtr, g_ptr);

    const int smem128 = 4 * 128 * RSTRIDE;                      // 139264
    const int smem64  = 2 * 64 * RSTRIDE + 2 * 128 * RSTRIDE;   // 104448
    cudaFuncSetAttribute(gemm_mma<128, false>, cudaFuncAttributeMaxDynamicSharedMemorySize, smem128);
    cudaFuncSetAttribute(gemm_mma<128, true>,  cudaFuncAttributeMaxDynamicSharedMemorySize, smem128);
    cudaFuncSetAttribute(gemm_mma<64, false>,  cudaFuncAttributeMaxDynamicSharedMemorySize, smem64);

    const int T = 256;
    const int gemmGrid = (N + 127) / 128;
    const int edgeThG  = (E + T - 1) / T;
    const int nodeThG  = (N + T - 1) / T;
    const int nodeWarpG = (N * 32 + T - 1) / T;
    const int scanBlocks = (N + 1023) / 1024;

    // ---- CSR build (by destination) + attention coef ----
    zero_deg_kernel<<<nodeThG, T>>>(N);
    hist_kernel<<<edgeThG, T>>>(row, col, E);
    coef_kernel<<<nodeThG, T>>>(N);
    scan_block_kernel<<<scanBlocks, 1024>>>(pPtr, N);   // partial scan into g_ptr (temp)
    scan_top_kernel<<<1, 32>>>(scanBlocks);
    finalize_kernel<<<nodeThG, T>>>(pPtr, N);           // writes g_start and resets g_ptr
    scatter_kernel<<<edgeThG, T>>>(row, col, E);

    // ---- network ----
    gemm_mma<128, false><<<gemmGrid, T, smem128>>>(x, fl_W, fl_b, pH, N);
    agg_kernel<true><<<nodeWarpG, T>>>(pH, pB, N);                       // h1 = relu(att-agg)
    agg_kernel<false><<<nodeWarpG, T>>>(pB, pC, N);                      // z1 = h1 + agg(h1)
    gemm_mma<128, true><<<gemmGrid, T, smem128>>>(pC, g1_W1, g1_b1, pH, N);
    gemm_mma<128, true><<<gemmGrid, T, smem128>>>(pH, g1_W2, g1_b2, pC, N);  // h2
    agg_kernel<false><<<nodeWarpG, T>>>(pC, pB, N);                      // z2 = h2 + agg(h2)
    gemm_mma<128, true><<<gemmGrid, T, smem128>>>(pB, g2_W1, g2_b1, pH, N);
    gemm_mma<128, true><<<gemmGrid, T, smem128>>>(pH, g2_W2, g2_b2, pB, N);  // h3
    gemm_mma<64, false><<<gemmGrid, T, smem64>>>(pB, out_W, out_b, out, N);
    lsm_kernel<<<nodeWarpG, T>>>(out, N);
}

// round 5
// speedup vs baseline: 2.2370x; 1.6041x over previous
#include <cuda_runtime.h>
#include <cuda_bf16.h>
#include <cstdint>
#include <cstddef>

#define MAXN 50000
#define MAXE 600000
#define HDIM 128

// -------------------- scratch --------------------
__device__ float g_h[(size_t)MAXN * HDIM];
__device__ float g_B[(size_t)MAXN * HDIM];
__device__ float g_C[(size_t)MAXN * HDIM];
__device__ int   g_indeg[MAXN];
__device__ int   g_outdeg[MAXN];
__device__ float g_coef[MAXN];
__device__ int   g_start[MAXN];
__device__ int   g_ptr[MAXN];
__device__ int   g_eid[MAXE];
__device__ int   g_blocksum[64];
__device__ __nv_bfloat16 g_Whi[6 * 16384];   // pre-split weights (hi)
__device__ __nv_bfloat16 g_Wlo[6 * 16384];   // pre-split weights (lo)

// -------------------- helpers --------------------
__device__ __forceinline__ uint32_t smem_u32(const void* p) {
    uint32_t a;
    asm("{ .reg .u64 t; cvta.to.shared.u64 t, %1; cvt.u32.u64 %0, t; }" : "=r"(a) : "l"(p));
    return a;
}
__device__ __forceinline__ void ldsm4(uint32_t* r, uint32_t addr) {
    asm volatile("ldmatrix.sync.aligned.m8n8.x4.shared.b16 {%0,%1,%2,%3}, [%4];"
                 : "=r"(r[0]), "=r"(r[1]), "=r"(r[2]), "=r"(r[3]) : "r"(addr));
}
__device__ __forceinline__ void mma_bf16(float* c, const uint32_t* a, uint32_t b0, uint32_t b1) {
    asm volatile("mma.sync.aligned.m16n8k16.row.col.f32.bf16.bf16.f32 "
                 "{%0,%1,%2,%3}, {%4,%5,%6,%7}, {%8,%9}, {%0,%1,%2,%3};"
                 : "+f"(c[0]), "+f"(c[1]), "+f"(c[2]), "+f"(c[3])
                 : "r"(a[0]), "r"(a[1]), "r"(a[2]), "r"(a[3]), "r"(b0), "r"(b1));
}

#define RSTRIDE 272
__device__ __forceinline__ uint32_t toff(int r, int k) {
    return (uint32_t)r * RSTRIDE + (uint32_t)k * 2;
}
__device__ __forceinline__ void cvt_store(char* hi, char* lo, uint32_t off, float4 v) {
    __nv_bfloat162 h01 = __floats2bfloat162_rn(v.x, v.y);
    float2 f01 = __bfloat1622float2(h01);
    __nv_bfloat162 l01 = __floats2bfloat162_rn(v.x - f01.x, v.y - f01.y);
    __nv_bfloat162 h23 = __floats2bfloat162_rn(v.z, v.w);
    float2 f23 = __bfloat1622float2(h23);
    __nv_bfloat162 l23 = __floats2bfloat162_rn(v.z - f23.x, v.w - f23.y);
    *(uint32_t*)(hi + off)     = *(uint32_t*)&h01;
    *(uint32_t*)(hi + off + 4) = *(uint32_t*)&h23;
    *(uint32_t*)(lo + off)     = *(uint32_t*)&l01;
    *(uint32_t*)(lo + off + 4) = *(uint32_t*)&l23;
}

// -------------------- weight pre-split: 5x(128x128) + 1x(64x128) --------------------
__global__ void wsplit_kernel(const float* __restrict__ w0, const float* __restrict__ w1,
                              const float* __restrict__ w2, const float* __restrict__ w3,
                              const float* __restrict__ w4, const float* __restrict__ w5)
{
    int i = blockIdx.x * blockDim.x + threadIdx.x;   // element index
    int m = i >> 14, off = i & 16383;
    if (m > 5 || (m == 5 && off >= 8192)) return;
    const float* src = (m == 0) ? w0 : (m == 1) ? w1 : (m == 2) ? w2
                     : (m == 3) ? w3 : (m == 4) ? w4 : w5;
    float v = src[off];
    __nv_bfloat16 h = __float2bfloat16_rn(v);
    g_Whi[m * 16384 + off] = h;
    g_Wlo[m * 16384 + off] = __float2bfloat16_rn(v - __bfloat162float(h));
}

// -------------------- HMMA GEMM: C[M,BN] = A[M,128] @ W[BN,128]^T + bias --------------------
// BM=64 rows, 256 threads (8 warps: 4 along M x 2 along N), 2 CTAs/SM. bf16 hi/lo, 3 passes.
template<int BN, bool RELU, bool LSM>
__global__ __launch_bounds__(256, 2) void gemm_mma(
    const float* __restrict__ A,
    const __nv_bfloat16* __restrict__ Whi, const __nv_bfloat16* __restrict__ Wlo,
    const float* __restrict__ bias, float* __restrict__ C, int M)
{
    constexpr int WN  = BN / 2;          // 64 or 32
    constexpr int NT8 = WN / 8;          // 8 or 4
    constexpr int AT  = 64 * RSTRIDE;    // 17408
    constexpr int WT  = BN * RSTRIDE;
    constexpr int OFF_WHI = 0;
    constexpr int OFF_WLO = WT;
    constexpr int OFF_AHI = 2 * WT;
    constexpr int OFF_ALO = 2 * WT + AT;

    extern __shared__ __align__(16) char smem[];
    const uint32_t sb = smem_u32(smem);
    const int tid = threadIdx.x, wid = tid >> 5, lane = tid & 31;
    const int row0 = blockIdx.x * 64;
    const int warp_m0 = (wid & 3) * 16;
    const int warp_n0 = (wid >> 2) * WN;

    // stage W (pre-split bf16, direct copy)
    for (int i = tid; i < BN * 16; i += 256) {
        int r = i >> 4, kc = i & 15;
        *(uint4*)(smem + OFF_WHI + toff(r, kc * 8)) = *(const uint4*)(Whi + r * 128 + kc * 8);
        *(uint4*)(smem + OFF_WLO + toff(r, kc * 8)) = *(const uint4*)(Wlo + r * 128 + kc * 8);
    }
    // stage A (fp32 -> hi/lo)
    for (int i = tid; i < 64 * 32; i += 256) {
        int r = i >> 5, k = (i & 31) * 4;
        float4 v = make_float4(0.f, 0.f, 0.f, 0.f);
        if (row0 + r < M) v = *(const float4*)(A + (size_t)(row0 + r) * 128 + k);
        cvt_store(smem + OFF_AHI, smem + OFF_ALO, toff(r, k), v);
    }
    __syncthreads();

    const int arow = lane & 15;
    const int ak   = (lane >> 4) * 8;
    const uint32_t aoff = (uint32_t)(warp_m0 + arow) * RSTRIDE + (uint32_t)ak * 2;
    const int brow = (lane & 7) + (lane >> 4) * 8;
    const int bk   = ((lane >> 3) & 1) * 8;
    const uint32_t boff = (uint32_t)(warp_n0 + brow) * RSTRIDE + (uint32_t)bk * 2;

    float acc[NT8][4];
    #pragma unroll
    for (int nt = 0; nt < NT8; nt++)
        #pragma unroll
        for (int q = 0; q < 4; q++) acc[nt][q] = 0.f;

    const uint32_t aHi = sb + OFF_AHI + aoff, aLo = sb + OFF_ALO + aoff;
    const uint32_t bHi = sb + OFF_WHI + boff, bLo = sb + OFF_WLO + boff;

    // passes (hi,hi) + (hi,lo) share the A-hi fragment
    #pragma unroll
    for (int ks = 0; ks < 8; ks++) {
        uint32_t af[4];
        ldsm4(af, aHi + ks * 32);
        uint32_t bfh[NT8 * 2], bfl[NT8 * 2];
        #pragma unroll
        for (int nt2 = 0; nt2 < NT8 / 2; nt2++) {
            ldsm4(bfh + nt2 * 4, bHi + nt2 * 16 * RSTRIDE + ks * 32);
            ldsm4(bfl + nt2 * 4, bLo + nt2 * 16 * RSTRIDE + ks * 32);
        }
        #pragma unroll
        for (int nt = 0; nt < NT8; nt++) {
            mma_bf16(acc[nt], af, bfh[nt * 2], bfh[nt * 2 + 1]);
            mma_bf16(acc[nt], af, bfl[nt * 2], bfl[nt * 2 + 1]);
        }
    }
    // pass (lo,hi)
    #pragma unroll
    for (int ks = 0; ks < 8; ks++) {
        uint32_t af[4];
        ldsm4(af, aLo + ks * 32);
        uint32_t bfh[NT8 * 2];
        #pragma unroll
        for (int nt2 = 0; nt2 < NT8 / 2; nt2++)
            ldsm4(bfh + nt2 * 4, bHi + nt2 * 16 * RSTRIDE + ks * 32);
        #pragma unroll
        for (int nt = 0; nt < NT8; nt++)
            mma_bf16(acc[nt], af, bfh[nt * 2], bfh[nt * 2 + 1]);
    }

    const int colq = (lane & 3) * 2;
    if (!LSM) {
        // direct gmem epilogue
        int r0 = row0 + warp_m0 + (lane >> 2);
        #pragma unroll
        for (int nt = 0; nt < NT8; nt++) {
            int col = warp_n0 + nt * 8 + colq;
            float2 b2 = *(const float2*)(bias + col);
            float2 o0, o1;
            o0.x = acc[nt][0] + b2.x; o0.y = acc[nt][1] + b2.y;
            o1.x = acc[nt][2] + b2.x; o1.y = acc[nt][3] + b2.y;
            if (RELU) {
                o0.x = fmaxf(o0.x, 0.f); o0.y = fmaxf(o0.y, 0.f);
                o1.x = fmaxf(o1.x, 0.f); o1.y = fmaxf(o1.y, 0.f);
            }
            if (r0 < M)     *(float2*)(C + (size_t)r0 * BN + col)       = o0;
            if (r0 + 8 < M) *(float2*)(C + (size_t)(r0 + 8) * BN + col) = o1;
        }
    } else {
        // fused log_softmax epilogue (BN == 64): stage to smem, reduce per row
        __syncthreads();                      // smem reads done; safe to overlay
        float* Cs = (float*)smem;             // [64][68]
        int rr = warp_m0 + (lane >> 2);
        #pragma unroll
        for (int nt = 0; nt < NT8; nt++) {
            int col = warp_n0 + nt * 8 + colq;
            float2 b2 = *(const float2*)(bias + col);
            Cs[rr * 68 + col]            = acc[nt][0] + b2.x;
            Cs[rr * 68 + col + 1]        = acc[nt][1] + b2.y;
            Cs[(rr + 8) * 68 + col]      = acc[nt][2] + b2.x;
            Cs[(rr + 8) * 68 + col + 1]  = acc[nt][3] + b2.y;
        }
        __syncthreads();
        #pragma unroll
        for (int it = 0; it < 8; it++) {
            int r = wid + it * 8;             // 0..63
            float2 v = *(float2*)&Cs[r * 68 + lane * 2];
            float m = fmaxf(v.x, v.y);
            #pragma unroll
            for (int o = 16; o; o >>= 1) m = fmaxf(m, __shfl_xor_sync(0xffffffffu, m, o));
            float s = expf(v.x - m) + expf(v.y - m);
            #pragma unroll
            for (int o = 16; o; o >>= 1) s += __shfl_xor_sync(0xffffffffu, s, o);
            float ls = logf(s) + m;
            int gr = row0 + r;
            if (gr < M) {
                float2 o2 = make_float2(v.x - ls, v.y - ls);
                *(float2*)(C + (size_t)gr * 64 + lane * 2) = o2;
            }
        }
    }
}

// -------------------- CSR build --------------------
__global__ void zero_deg_kernel(int n) {
    int i = blockIdx.x * blockDim.x + threadIdx.x;
    if (i < n) { g_indeg[i] = 0; g_outdeg[i] = 0; }
}
__global__ void hist_kernel(const int* __restrict__ row, const int* __restrict__ col, int E) {
    int e = blockIdx.x * blockDim.x + threadIdx.x;
    if (e >= E) return;
    atomicAdd(&g_indeg[col[e]], 1);
    atomicAdd(&g_outdeg[row[e]], 1);
}
__global__ __launch_bounds__(1024) void scan_block_kernel(int* __restrict__ out, int n) {
    __shared__ int wsum[32];
    int i = blockIdx.x * 1024 + threadIdx.x;
    int lane = threadIdx.x & 31, wid = threadIdx.x >> 5;
    int orig = (i < n) ? g_indeg[i] : 0;
    int v = orig;
    #pragma unroll
    for (int o = 1; o < 32; o <<= 1) {
        int t = __shfl_up_sync(0xffffffffu, v, o);
        if (lane >= o) v += t;
    }
    if (lane == 31) wsum[wid] = v;
    __syncthreads();
    if (wid == 0) {
        int s = wsum[lane];
        #pragma unroll
        for (int o = 1; o < 32; o <<= 1) {
            int t = __shfl_up_sync(0xffffffffu, s, o);
            if (lane >= o) s += t;
        }
        wsum[lane] = s;
    }
    __syncthreads();
    int excl = v - orig + (wid > 0 ? wsum[wid - 1] : 0);
    if (i < n) out[i] = excl;
    if (threadIdx.x == 1023) g_blocksum[blockIdx.x] = excl + orig;
}
__global__ void scan_top_kernel(int nb) {
    if (threadIdx.x == 0) {
        int acc = 0;
        for (int b = 0; b < nb; b++) { int t = g_blocksum[b]; g_blocksum[b] = acc; acc += t; }
    }
}
__global__ void finalize_kernel(const int* __restrict__ partial, int n) {
    int i = blockIdx.x * blockDim.x + threadIdx.x;
    if (i >= n) return;
    int s = partial[i] + g_blocksum[i >> 10];
    g_start[i] = s;
    g_ptr[i]   = s;
    g_coef[i]  = 1.0f / (float)(g_outdeg[i] + 1);
}
__global__ void scatter_kernel(const int* __restrict__ row, const int* __restrict__ col, int E) {
    int e = blockIdx.x * blockDim.x + threadIdx.x;
    if (e >= E) return;
    int p = atomicAdd(&g_ptr[col[e]], 1);
    g_eid[p] = row[e];
}

// -------------------- gather aggregation (warp per node, batched eids) --------------------
template<bool ATT>
__global__ void agg_kernel(const float* __restrict__ src, float* __restrict__ dst, int n) {
    int node = (blockIdx.x * blockDim.x + threadIdx.x) >> 5;
    int lane = threadIdx.x & 31;
    if (node >= n) return;
    int s = g_start[node], e = s + g_indeg[node];
    float4 acc = *(const float4*)(src + (size_t)node * 128 + lane * 4);
    if (ATT) {
        float c = g_coef[node];
        acc.x *= c; acc.y *= c; acc.z *= c; acc.w *= c;
    }
    for (int j0 = s; j0 < e; j0 += 32) {
        int nb = min(32, e - j0);
        int myeid = (lane < nb) ? __ldg(&g_eid[j0 + lane]) : 0;
        for (int t = 0; t < nb; t++) {
            int r = __shfl_sync(0xffffffffu, myeid, t);
            float4 v = *(const float4*)(src + (size_t)r * 128 + lane * 4);
            float c = ATT ? g_coef[r] : 1.0f;
            acc.x = fmaf(c, v.x, acc.x); acc.y = fmaf(c, v.y, acc.y);
            acc.z = fmaf(c, v.z, acc.z); acc.w = fmaf(c, v.w, acc.w);
        }
    }
    if (ATT) {
        acc.x = fmaxf(acc.x, 0.f); acc.y = fmaxf(acc.y, 0.f);
        acc.z = fmaxf(acc.z, 0.f); acc.w = fmaxf(acc.w, 0.f);
    }
    *(float4*)(dst + (size_t)node * 128 + lane * 4) = acc;
}

// -------------------- launch --------------------
extern "C" void kernel_launch(void* const* d_in, const int* in_sizes, int n_in,
                              void* d_out, int out_size)
{
    const float* x     = (const float*)d_in[0];
    const int*   ei    = (const int*)  d_in[1];
    const float* fl_W  = (const float*)d_in[2];
    const float* fl_b  = (const float*)d_in[3];
    // d_in[4] = fl_att : softmax over identical per-segment logits is uniform -> unused
    const float* g1_W1 = (const float*)d_in[5];
    const float* g1_b1 = (const float*)d_in[6];
    const float* g1_W2 = (const float*)d_in[7];
    const float* g1_b2 = (const float*)d_in[8];
    const float* g2_W1 = (const float*)d_in[9];
    const float* g2_b1 = (const float*)d_in[10];
    const float* g2_W2 = (const float*)d_in[11];
    const float* g2_b2 = (const float*)d_in[12];
    const float* out_W = (const float*)d_in[13];
    const float* out_b = (const float*)d_in[14];
    float* out = (float*)d_out;

    const int N = in_sizes[0] / HDIM;
    const int E = in_sizes[1] / 2;
    const int* row = ei;
    const int* col = ei + E;

    float *pH = nullptr, *pB = nullptr, *pC = nullptr;
    int* pPtr = nullptr;
    __nv_bfloat16 *pWhi = nullptr, *pWlo = nullptr;
    cudaGetSymbolAddress((void**)&pH, g_h);
    cudaGetSymbolAddress((void**)&pB, g_B);
    cudaGetSymbolAddress((void**)&pC, g_C);
    cudaGetSymbolAddress((void**)&pPtr, g_ptr);
    cudaGetSymbolAddress((void**)&pWhi, g_Whi);
    cudaGetSymbolAddress((void**)&pWlo, g_Wlo);

    const int smem128 = 2 * 128 * RSTRIDE + 2 * 64 * RSTRIDE;  // 104448
    const int smem64  = 4 * 64 * RSTRIDE;                      // 69632
    cudaFuncSetAttribute(gemm_mma<128, false, false>, cudaFuncAttributeMaxDynamicSharedMemorySize, smem128);
    cudaFuncSetAttribute(gemm_mma<128, true,  false>, cudaFuncAttributeMaxDynamicSharedMemorySize, smem128);
    cudaFuncSetAttribute(gemm_mma<64,  false, true>,  cudaFuncAttributeMaxDynamicSharedMemorySize, smem64);

    const int T = 256;
    const int gemmGrid  = (N + 63) / 64;
    const int edgeThG   = (E + T - 1) / T;
    const int nodeThG   = (N + T - 1) / T;
    const int nodeWarpG = (N * 32 + T - 1) / T;
    const int scanBlocks = (N + 1023) / 1024;

    // ---- weight pre-split + CSR build ----
    wsplit_kernel<<<(6 * 16384 + T - 1) / T, T>>>(fl_W, g1_W1, g1_W2, g2_W1, g2_W2, out_W);
    zero_deg_kernel<<<nodeThG, T>>>(N);
    hist_kernel<<<edgeThG, T>>>(row, col, E);
    scan_block_kernel<<<scanBlocks, 1024>>>(pPtr, N);
    scan_top_kernel<<<1, 32>>>(scanBlocks);
    finalize_kernel<<<nodeThG, T>>>(pPtr, N);
    scatter_kernel<<<edgeThG, T>>>(row, col, E);

    // ---- network ----
    gemm_mma<128, false, false><<<gemmGrid, T, smem128>>>(x, pWhi, pWlo, fl_b, pH, N);
    agg_kernel<true><<<nodeWarpG, T>>>(pH, pB, N);
    agg_kernel<false><<<nodeWarpG, T>>>(pB, pC, N);
    gemm_mma<128, true, false><<<gemmGrid, T, smem128>>>(pC, pWhi + 16384, pWlo + 16384, g1_b1, pH, N);
    gemm_mma<128, true, false><<<gemmGrid, T, smem128>>>(pH, pWhi + 2 * 16384, pWlo + 2 * 16384, g1_b2, pC, N);
    agg_kernel<false><<<nodeWarpG, T>>>(pC, pB, N);
    gemm_mma<128, true, false><<<gemmGrid, T, smem128>>>(pB, pWhi + 3 * 16384, pWlo + 3 * 16384, g2_b1, pH, N);
    gemm_mma<128, true, false><<<gemmGrid, T, smem128>>>(pH, pWhi + 4 * 16384, pWlo + 4 * 16384, g2_b2, pB, N);
    gemm_mma<64, false, true><<<gemmGrid, T, smem64>>>(pB, pWhi + 5 * 16384, pWlo + 5 * 16384, out_b, out, N);
}

// round 6
// speedup vs baseline: 2.4081x; 1.0765x over previous
#include <cuda_runtime.h>
#include <cuda_bf16.h>
#include <cstdint>
#include <cstddef>

#define MAXN 50000
#define MAXE 600000
#define HDIM 128

// -------------------- scratch --------------------
__device__ float g_h[(size_t)MAXN * HDIM];
__device__ float g_B[(size_t)MAXN * HDIM];
__device__ float g_C[(size_t)MAXN * HDIM];
__device__ int   g_indeg[MAXN];
__device__ int   g_outdeg[MAXN];
__device__ float g_coef[MAXN];
__device__ int   g_start[MAXN];
__device__ int   g_ptr[MAXN];
__device__ int   g_eid[MAXE];
__device__ int   g_blocksum[64];
__device__ __nv_bfloat16 g_Whi[6 * 16384];
__device__ __nv_bfloat16 g_Wlo[6 * 16384];

// -------------------- helpers --------------------
__device__ __forceinline__ uint32_t smem_u32(const void* p) {
    uint32_t a;
    asm("{ .reg .u64 t; cvta.to.shared.u64 t, %1; cvt.u32.u64 %0, t; }" : "=r"(a) : "l"(p));
    return a;
}
__device__ __forceinline__ void ldsm4(uint32_t* r, uint32_t addr) {
    asm volatile("ldmatrix.sync.aligned.m8n8.x4.shared.b16 {%0,%1,%2,%3}, [%4];"
                 : "=r"(r[0]), "=r"(r[1]), "=r"(r[2]), "=r"(r[3]) : "r"(addr));
}
__device__ __forceinline__ void mma_bf16(float* c, const uint32_t* a, uint32_t b0, uint32_t b1) {
    asm volatile("mma.sync.aligned.m16n8k16.row.col.f32.bf16.bf16.f32 "
                 "{%0,%1,%2,%3}, {%4,%5,%6,%7}, {%8,%9}, {%0,%1,%2,%3};"
                 : "+f"(c[0]), "+f"(c[1]), "+f"(c[2]), "+f"(c[3])
                 : "r"(a[0]), "r"(a[1]), "r"(a[2]), "r"(a[3]), "r"(b0), "r"(b1));
}

#define RSTRIDE 272
__device__ __forceinline__ uint32_t toff(int r, int k) {
    return (uint32_t)r * RSTRIDE + (uint32_t)k * 2;
}
__device__ __forceinline__ void cvt_store(char* hi, char* lo, uint32_t off, float4 v) {
    __nv_bfloat162 h01 = __floats2bfloat162_rn(v.x, v.y);
    float2 f01 = __bfloat1622float2(h01);
    __nv_bfloat162 l01 = __floats2bfloat162_rn(v.x - f01.x, v.y - f01.y);
    __nv_bfloat162 h23 = __floats2bfloat162_rn(v.z, v.w);
    float2 f23 = __bfloat1622float2(h23);
    __nv_bfloat162 l23 = __floats2bfloat162_rn(v.z - f23.x, v.w - f23.y);
    *(uint32_t*)(hi + off)     = *(uint32_t*)&h01;
    *(uint32_t*)(hi + off + 4) = *(uint32_t*)&h23;
    *(uint32_t*)(lo + off)     = *(uint32_t*)&l01;
    *(uint32_t*)(lo + off + 4) = *(uint32_t*)&l23;
}

// -------------------- weight pre-split --------------------
__global__ void wsplit_kernel(const float* __restrict__ w0, const float* __restrict__ w1,
                              const float* __restrict__ w2, const float* __restrict__ w3,
                              const float* __restrict__ w4, const float* __restrict__ w5)
{
    int i = blockIdx.x * blockDim.x + threadIdx.x;
    int m = i >> 14, off = i & 16383;
    if (m > 5 || (m == 5 && off >= 8192)) return;
    const float* src = (m == 0) ? w0 : (m == 1) ? w1 : (m == 2) ? w2
                     : (m == 3) ? w3 : (m == 4) ? w4 : w5;
    float v = src[off];
    __nv_bfloat16 h = __float2bfloat16_rn(v);
    g_Whi[m * 16384 + off] = h;
    g_Wlo[m * 16384 + off] = __float2bfloat16_rn(v - __bfloat162float(h));
}

// -------------------- HMMA GEMM (BM=64, 2 CTAs/SM, bf16 hi/lo 3-pass) --------------------
template<int BN, bool RELU, bool LSM>
__global__ __launch_bounds__(256, 2) void gemm_mma(
    const float* __restrict__ A,
    const __nv_bfloat16* __restrict__ Whi, const __nv_bfloat16* __restrict__ Wlo,
    const float* __restrict__ bias, float* __restrict__ C, int M)
{
    constexpr int WN  = BN / 2;
    constexpr int NT8 = WN / 8;
    constexpr int AT  = 64 * RSTRIDE;
    constexpr int WT  = BN * RSTRIDE;
    constexpr int OFF_WHI = 0;
    constexpr int OFF_WLO = WT;
    constexpr int OFF_AHI = 2 * WT;
    constexpr int OFF_ALO = 2 * WT + AT;

    extern __shared__ __align__(16) char smem[];
    const uint32_t sb = smem_u32(smem);
    const int tid = threadIdx.x, wid = tid >> 5, lane = tid & 31;
    const int row0 = blockIdx.x * 64;
    const int warp_m0 = (wid & 3) * 16;
    const int warp_n0 = (wid >> 2) * WN;

    for (int i = tid; i < BN * 16; i += 256) {
        int r = i >> 4, kc = i & 15;
        *(uint4*)(smem + OFF_WHI + toff(r, kc * 8)) = *(const uint4*)(Whi + r * 128 + kc * 8);
        *(uint4*)(smem + OFF_WLO + toff(r, kc * 8)) = *(const uint4*)(Wlo + r * 128 + kc * 8);
    }
    for (int i = tid; i < 64 * 32; i += 256) {
        int r = i >> 5, k = (i & 31) * 4;
        float4 v = make_float4(0.f, 0.f, 0.f, 0.f);
        if (row0 + r < M) v = *(const float4*)(A + (size_t)(row0 + r) * 128 + k);
        cvt_store(smem + OFF_AHI, smem + OFF_ALO, toff(r, k), v);
    }
    __syncthreads();

    const int arow = lane & 15;
    const int ak   = (lane >> 4) * 8;
    const uint32_t aoff = (uint32_t)(warp_m0 + arow) * RSTRIDE + (uint32_t)ak * 2;
    const int brow = (lane & 7) + (lane >> 4) * 8;
    const int bk   = ((lane >> 3) & 1) * 8;
    const uint32_t boff = (uint32_t)(warp_n0 + brow) * RSTRIDE + (uint32_t)bk * 2;

    float acc[NT8][4];
    #pragma unroll
    for (int nt = 0; nt < NT8; nt++)
        #pragma unroll
        for (int q = 0; q < 4; q++) acc[nt][q] = 0.f;

    const uint32_t aHi = sb + OFF_AHI + aoff, aLo = sb + OFF_ALO + aoff;
    const uint32_t bHi = sb + OFF_WHI + boff, bLo = sb + OFF_WLO + boff;

    #pragma unroll
    for (int ks = 0; ks < 8; ks++) {
        uint32_t af[4];
        ldsm4(af, aHi + ks * 32);
        uint32_t bfh[NT8 * 2], bfl[NT8 * 2];
        #pragma unroll
        for (int nt2 = 0; nt2 < NT8 / 2; nt2++) {
            ldsm4(bfh + nt2 * 4, bHi + nt2 * 16 * RSTRIDE + ks * 32);
            ldsm4(bfl + nt2 * 4, bLo + nt2 * 16 * RSTRIDE + ks * 32);
        }
        #pragma unroll
        for (int nt = 0; nt < NT8; nt++) {
            mma_bf16(acc[nt], af, bfh[nt * 2], bfh[nt * 2 + 1]);
            mma_bf16(acc[nt], af, bfl[nt * 2], bfl[nt * 2 + 1]);
        }
    }
    #pragma unroll
    for (int ks = 0; ks < 8; ks++) {
        uint32_t af[4];
        ldsm4(af, aLo + ks * 32);
        uint32_t bfh[NT8 * 2];
        #pragma unroll
        for (int nt2 = 0; nt2 < NT8 / 2; nt2++)
            ldsm4(bfh + nt2 * 4, bHi + nt2 * 16 * RSTRIDE + ks * 32);
        #pragma unroll
        for (int nt = 0; nt < NT8; nt++)
            mma_bf16(acc[nt], af, bfh[nt * 2], bfh[nt * 2 + 1]);
    }

    const int colq = (lane & 3) * 2;
    if (!LSM) {
        int r0 = row0 + warp_m0 + (lane >> 2);
        #pragma unroll
        for (int nt = 0; nt < NT8; nt++) {
            int col = warp_n0 + nt * 8 + colq;
            float2 b2 = *(const float2*)(bias + col);
            float2 o0, o1;
            o0.x = acc[nt][0] + b2.x; o0.y = acc[nt][1] + b2.y;
            o1.x = acc[nt][2] + b2.x; o1.y = acc[nt][3] + b2.y;
            if (RELU) {
                o0.x = fmaxf(o0.x, 0.f); o0.y = fmaxf(o0.y, 0.f);
                o1.x = fmaxf(o1.x, 0.f); o1.y = fmaxf(o1.y, 0.f);
            }
            if (r0 < M)     *(float2*)(C + (size_t)r0 * BN + col)       = o0;
            if (r0 + 8 < M) *(float2*)(C + (size_t)(r0 + 8) * BN + col) = o1;
        }
    } else {
        __syncthreads();
        float* Cs = (float*)smem;  // [64][68]
        int rr = warp_m0 + (lane >> 2);
        #pragma unroll
        for (int nt = 0; nt < NT8; nt++) {
            int col = warp_n0 + nt * 8 + colq;
            float2 b2 = *(const float2*)(bias + col);
            Cs[rr * 68 + col]            = acc[nt][0] + b2.x;
            Cs[rr * 68 + col + 1]        = acc[nt][1] + b2.y;
            Cs[(rr + 8) * 68 + col]      = acc[nt][2] + b2.x;
            Cs[(rr + 8) * 68 + col + 1]  = acc[nt][3] + b2.y;
        }
        __syncthreads();
        #pragma unroll
        for (int it = 0; it < 8; it++) {
            int r = wid + it * 8;
            float2 v = *(float2*)&Cs[r * 68 + lane * 2];
            float m = fmaxf(v.x, v.y);
            #pragma unroll
            for (int o = 16; o; o >>= 1) m = fmaxf(m, __shfl_xor_sync(0xffffffffu, m, o));
            float s = expf(v.x - m) + expf(v.y - m);
            #pragma unroll
            for (int o = 16; o; o >>= 1) s += __shfl_xor_sync(0xffffffffu, s, o);
            float ls = logf(s) + m;
            int gr = row0 + r;
            if (gr < M)
                *(float2*)(C + (size_t)gr * 64 + lane * 2) = make_float2(v.x - ls, v.y - ls);
        }
    }
}

// -------------------- CSR build --------------------
__global__ void zero_deg_kernel(int n) {
    int i = blockIdx.x * blockDim.x + threadIdx.x;
    if (i < n) { g_indeg[i] = 0; g_outdeg[i] = 0; }
}
__global__ void hist_kernel(const int* __restrict__ row, const int* __restrict__ col, int E) {
    int e = blockIdx.x * blockDim.x + threadIdx.x;
    if (e >= E) return;
    atomicAdd(&g_indeg[col[e]], 1);
    atomicAdd(&g_outdeg[row[e]], 1);
}
__global__ __launch_bounds__(1024) void scan_block_kernel(int* __restrict__ out, int n) {
    __shared__ int wsum[32];
    int i = blockIdx.x * 1024 + threadIdx.x;
    int lane = threadIdx.x & 31, wid = threadIdx.x >> 5;
    int orig = (i < n) ? g_indeg[i] : 0;
    int v = orig;
    #pragma unroll
    for (int o = 1; o < 32; o <<= 1) {
        int t = __shfl_up_sync(0xffffffffu, v, o);
        if (lane >= o) v += t;
    }
    if (lane == 31) wsum[wid] = v;
    __syncthreads();
    if (wid == 0) {
        int s = wsum[lane];
        #pragma unroll
        for (int o = 1; o < 32; o <<= 1) {
            int t = __shfl_up_sync(0xffffffffu, s, o);
            if (lane >= o) s += t;
        }
        wsum[lane] = s;
    }
    __syncthreads();
    int excl = v - orig + (wid > 0 ? wsum[wid - 1] : 0);
    if (i < n) out[i] = excl;
    if (threadIdx.x == 1023) g_blocksum[blockIdx.x] = excl + orig;
}
// parallel exclusive scan of <=64 block sums (one 64-thread block)
__global__ void scan_top_kernel(int nb) {
    __shared__ int ws[2];
    int t = threadIdx.x, lane = t & 31, w = t >> 5;
    int v = (t < nb) ? g_blocksum[t] : 0;
    int s = v;
    #pragma unroll
    for (int o = 1; o < 32; o <<= 1) {
        int x = __shfl_up_sync(0xffffffffu, s, o);
        if (lane >= o) s += x;
    }
    if (lane == 31) ws[w] = s;
    __syncthreads();
    int excl = s - v + (w == 1 ? ws[0] : 0);
    if (t < nb) g_blocksum[t] = excl;
}
__global__ void finalize_kernel(const int* __restrict__ partial, int n) {
    int i = blockIdx.x * blockDim.x + threadIdx.x;
    if (i >= n) return;
    int s = partial[i] + g_blocksum[i >> 10];
    g_start[i] = s;
    g_ptr[i]   = s;
    g_coef[i]  = 1.0f / (float)(g_outdeg[i] + 1);
}
__global__ void scatter_kernel(const int* __restrict__ row, const int* __restrict__ col, int E) {
    int e = blockIdx.x * blockDim.x + threadIdx.x;
    if (e >= E) return;
    int p = atomicAdd(&g_ptr[col[e]], 1);
    g_eid[p] = row[e];
}

// -------------------- gather aggregation (warp per node, 2-deep pipelined) --------------------
template<bool ATT>
__global__ void agg_kernel(const float* __restrict__ src, float* __restrict__ dst, int n) {
    int node = (blockIdx.x * blockDim.x + threadIdx.x) >> 5;
    int lane = threadIdx.x & 31;
    if (node >= n) return;
    int s = g_start[node], e = s + g_indeg[node];
    float4 acc = *(const float4*)(src + (size_t)node * 128 + lane * 4);
    if (ATT) {
        float c = g_coef[node];
        acc.x *= c; acc.y *= c; acc.z *= c; acc.w *= c;
    }
    float4 acc2 = make_float4(0.f, 0.f, 0.f, 0.f);
    for (int j0 = s; j0 < e; j0 += 32) {
        int nb = min(32, e - j0);
        int myeid = (lane < nb) ? __ldg(&g_eid[j0 + lane]) : 0;
        int t = 0;
        for (; t + 1 < nb; t += 2) {
            int r0 = __shfl_sync(0xffffffffu, myeid, t);
            int r1 = __shfl_sync(0xffffffffu, myeid, t + 1);
            float4 v0 = *(const float4*)(src + (size_t)r0 * 128 + lane * 4);
            float4 v1 = *(const float4*)(src + (size_t)r1 * 128 + lane * 4);
            float c0 = ATT ? g_coef[r0] : 1.0f;
            float c1 = ATT ? g_coef[r1] : 1.0f;
            acc.x  = fmaf(c0, v0.x, acc.x);  acc.y  = fmaf(c0, v0.y, acc.y);
            acc.z  = fmaf(c0, v0.z, acc.z);  acc.w  = fmaf(c0, v0.w, acc.w);
            acc2.x = fmaf(c1, v1.x, acc2.x); acc2.y = fmaf(c1, v1.y, acc2.y);
            acc2.z = fmaf(c1, v1.z, acc2.z); acc2.w = fmaf(c1, v1.w, acc2.w);
        }
        if (t < nb) {
            int r0 = __shfl_sync(0xffffffffu, myeid, t);
            float4 v0 = *(const float4*)(src + (size_t)r0 * 128 + lane * 4);
            float c0 = ATT ? g_coef[r0] : 1.0f;
            acc.x = fmaf(c0, v0.x, acc.x); acc.y = fmaf(c0, v0.y, acc.y);
            acc.z = fmaf(c0, v0.z, acc.z); acc.w = fmaf(c0, v0.w, acc.w);
        }
    }
    acc.x += acc2.x; acc.y += acc2.y; acc.z += acc2.z; acc.w += acc2.w;
    if (ATT) {
        acc.x = fmaxf(acc.x, 0.f); acc.y = fmaxf(acc.y, 0.f);
        acc.z = fmaxf(acc.z, 0.f); acc.w = fmaxf(acc.w, 0.f);
    }
    *(float4*)(dst + (size_t)node * 128 + lane * 4) = acc;
}

// -------------------- launch --------------------
extern "C" void kernel_launch(void* const* d_in, const int* in_sizes, int n_in,
                              void* d_out, int out_size)
{
    const float* x     = (const float*)d_in[0];
    const int*   ei    = (const int*)  d_in[1];
    const float* fl_W  = (const float*)d_in[2];
    const float* fl_b  = (const float*)d_in[3];
    // d_in[4] = fl_att : softmax over identical per-segment logits is uniform -> unused
    const float* g1_W1 = (const float*)d_in[5];
    const float* g1_b1 = (const float*)d_in[6];
    const float* g1_W2 = (const float*)d_in[7];
    const float* g1_b2 = (const float*)d_in[8];
    const float* g2_W1 = (const float*)d_in[9];
    const float* g2_b1 = (const float*)d_in[10];
    const float* g2_W2 = (const float*)d_in[11];
    const float* g2_b2 = (const float*)d_in[12];
    const float* out_W = (const float*)d_in[13];
    const float* out_b = (const float*)d_in[14];
    float* out = (float*)d_out;

    const int N = in_sizes[0] / HDIM;
    const int E = in_sizes[1] / 2;
    const int* row = ei;
    const int* col = ei + E;

    float *pH = nullptr, *pB = nullptr, *pC = nullptr;
    int* pPtr = nullptr;
    __nv_bfloat16 *pWhi = nullptr, *pWlo = nullptr;
    cudaGetSymbolAddress((void**)&pH, g_h);
    cudaGetSymbolAddress((void**)&pB, g_B);
    cudaGetSymbolAddress((void**)&pC, g_C);
    cudaGetSymbolAddress((void**)&pPtr, g_ptr);
    cudaGetSymbolAddress((void**)&pWhi, g_Whi);
    cudaGetSymbolAddress((void**)&pWlo, g_Wlo);

    const int smem128 = 2 * 128 * RSTRIDE + 2 * 64 * RSTRIDE;  // 104448
    const int smem64  = 4 * 64 * RSTRIDE;                      // 69632
    cudaFuncSetAttribute(gemm_mma<128, false, false>, cudaFuncAttributeMaxDynamicSharedMemorySize, smem128);
    cudaFuncSetAttribute(gemm_mma<128, true,  false>, cudaFuncAttributeMaxDynamicSharedMemorySize, smem128);
    cudaFuncSetAttribute(gemm_mma<64,  false, true>,  cudaFuncAttributeMaxDynamicSharedMemorySize, smem64);

    // side stream + events for captured fork/join (created on first, non-capture call)
    static cudaStream_t s_side = [] {
        cudaStream_t s; cudaStreamCreateWithFlags(&s, cudaStreamNonBlocking); return s;
    }();
    static cudaEvent_t s_fork = [] {
        cudaEvent_t e; cudaEventCreateWithFlags(&e, cudaEventDisableTiming); return e;
    }();
    static cudaEvent_t s_join = [] {
        cudaEvent_t e; cudaEventCreateWithFlags(&e, cudaEventDisableTiming); return e;
    }();

    const int T = 256;
    const int gemmGrid  = (N + 63) / 64;
    const int edgeThG   = (E + T - 1) / T;
    const int nodeThG   = (N + T - 1) / T;
    const int nodeWarpG = (N * 32 + T - 1) / T;
    const int scanBlocks = (N + 1023) / 1024;

    // ---- fork: CSR build on side stream, wsplit+gemm1 on main ----
    cudaEventRecord(s_fork, 0);
    cudaStreamWaitEvent(s_side, s_fork, 0);

    zero_deg_kernel<<<nodeThG, T, 0, s_side>>>(N);
    hist_kernel<<<edgeThG, T, 0, s_side>>>(row, col, E);
    scan_block_kernel<<<scanBlocks, 1024, 0, s_side>>>(pPtr, N);
    scan_top_kernel<<<1, 64, 0, s_side>>>(scanBlocks);
    finalize_kernel<<<nodeThG, T, 0, s_side>>>(pPtr, N);
    scatter_kernel<<<edgeThG, T, 0, s_side>>>(row, col, E);
    cudaEventRecord(s_join, s_side);

    wsplit_kernel<<<(6 * 16384 + T - 1) / T, T>>>(fl_W, g1_W1, g1_W2, g2_W1, g2_W2, out_W);
    gemm_mma<128, false, false><<<gemmGrid, T, smem128>>>(x, pWhi, pWlo, fl_b, pH, N);

    cudaStreamWaitEvent(0, s_join, 0);   // join before first aggregation

    // ---- network ----
    agg_kernel<true><<<nodeWarpG, T>>>(pH, pB, N);
    agg_kernel<false><<<nodeWarpG, T>>>(pB, pC, N);
    gemm_mma<128, true, false><<<gemmGrid, T, smem128>>>(pC, pWhi + 16384, pWlo + 16384, g1_b1, pH, N);
    gemm_mma<128, true, false><<<gemmGrid, T, smem128>>>(pH, pWhi + 2 * 16384, pWlo + 2 * 16384, g1_b2, pC, N);
    agg_kernel<false><<<nodeWarpG, T>>>(pC, pB, N);
    gemm_mma<128, true, false><<<gemmGrid, T, smem128>>>(pB, pWhi + 3 * 16384, pWlo + 3 * 16384, g2_b1, pH, N);
    gemm_mma<128, true, false><<<gemmGrid, T, smem128>>>(pH, pWhi + 4 * 16384, pWlo + 4 * 16384, g2_b2, pB, N);
    gemm_mma<64, false, true><<<gemmGrid, T, smem64>>>(pB, pWhi + 5 * 16384, pWlo + 5 * 16384, out_b, out, N);
}